// round 16
// baseline (speedup 1.0000x reference)
#include <cuda_runtime.h>
#include <cuda_fp16.h>
#include <cstdint>

// Problem dims
#define B_ROWS 8192
#define KDIM   4096
#define NDIM   4096
#define CAPQ   492

// GEMM tiling: CTA 128x256, 8 warps as 2(M) x 4(N), warp tile 64x64.
// BK=128 (256B rows) -> 32 stages/tile; 2-slot mbarrier ring, persistent CTAs.
#define BM 128
#define BN 256
#define BK 128
#define STAGES 2
#define MT (B_ROWS / BM)               // 64
#define NT (NDIM / BN)                 // 16
#define KT (KDIM / BK)                 // 32  (l>>5 / l&31 below)
#define TT (MT * NT)                   // 1024 tiles
#define A_BYTES (BM * BK * 2)          // 32768
#define B_BYTES (BN * BK * 2)          // 65536
#define STAGE_BYTES (A_BYTES + B_BYTES)      // 98304
#define SMEM_SIZE (128 + STAGES * STAGE_BYTES)   // 196736

// Scratch (allocations forbidden -> __device__ globals)
__device__ __half g_Wh[(size_t)NDIM * KDIM];   // half W, [n][k]
__device__ __half g_xh[(size_t)B_ROWS * KDIM]; // half x, [m][k]

// 256B-row swizzle: XOR 16B-chunk index within each 128B half by (row & 7)
__device__ __forceinline__ uint32_t swz(int r, int c16) {
    return (uint32_t)(r * 256 + ((((c16 & 7) ^ (r & 7)) | (c16 & 8)) << 4));
}

// ----------------------------------------------------------- mbarrier utils -
__device__ __forceinline__ void mbar_init(uint32_t a, uint32_t cnt) {
    asm volatile("mbarrier.init.shared.b64 [%0], %1;" :: "r"(a), "r"(cnt) : "memory");
}
__device__ __forceinline__ void mbar_arrive(uint32_t a) {
    asm volatile("mbarrier.arrive.shared.b64 _, [%0];" :: "r"(a) : "memory");
}
__device__ __forceinline__ void cpasync_mbar_arrive(uint32_t a) {
    // .noinc is load-bearing (default form pre-increments expected count -> hang)
    asm volatile("cp.async.mbarrier.arrive.noinc.shared.b64 [%0];" :: "r"(a) : "memory");
}
// acquire-form wait: ordering built into the trywait, no separate fence
__device__ __forceinline__ void mbar_wait(uint32_t a, uint32_t parity) {
    uint32_t done;
    asm volatile(
        "{\n\t.reg .pred p;\n\t"
        "mbarrier.try_wait.parity.acquire.cta.shared::cta.b64 p, [%1], %2;\n\t"
        "selp.b32 %0, 1, 0, p;\n\t}"
        : "=r"(done) : "r"(a), "r"(parity) : "memory");
    while (!done) {
        asm volatile(
            "{\n\t.reg .pred p;\n\t"
            "mbarrier.try_wait.parity.acquire.cta.shared::cta.b64 p, [%1], %2, 0x989680;\n\t"
            "selp.b32 %0, 1, 0, p;\n\t}"
            : "=r"(done) : "r"(a), "r"(parity) : "memory");
    }
}

// ------------------------------------------------------------ fused prep ----
// Interleaved block types: bid%3==0 -> cvt x (2048 blocks), else build_w (4096).
#define CVT_BLOCKS 2048
#define PREP_BLOCKS (NDIM + CVT_BLOCKS)   // 6144
__global__ __launch_bounds__(256)
void prep_kernel(const float* __restrict__ values, const int* __restrict__ col,
                 const float4* __restrict__ x) {
    __shared__ float row[KDIM];
    const int tid = threadIdx.x;
    const int bid = blockIdx.x;

    if (bid % 3 != 0) {
        const int o = bid - bid / 3 - 1;          // 0..NDIM-1
        float4* r4 = (float4*)row;
        #pragma unroll
        for (int i = 0; i < KDIM / 4 / 256; i++)
            r4[i * 256 + tid] = make_float4(0.f, 0.f, 0.f, 0.f);
        __syncthreads();

        const float* v = values + (size_t)o * CAPQ;
        const int*   c = col    + (size_t)o * CAPQ;
        for (int s = tid; s < CAPQ; s += 256) {
            float val = v[s];
            if (val != 0.0f) atomicAdd(&row[c[s]], val);
        }
        __syncthreads();

        __half2* out = (__half2*)(g_Wh + (size_t)o * KDIM);
        #pragma unroll
        for (int i = 0; i < KDIM / 4 / 256; i++) {
            float4 f = r4[i * 256 + tid];
            int j = (i * 256 + tid) * 2;
            out[j]     = __floats2half2_rn(f.x, f.y);
            out[j + 1] = __floats2half2_rn(f.z, f.w);
        }
    } else {
        const int cb = bid / 3;                   // 0..CVT_BLOCKS-1
        const size_t n4 = (size_t)B_ROWS * KDIM / 4;
        __half2* out = (__half2*)g_xh;
        for (size_t i = (size_t)cb * 256 + tid; i < n4;
             i += (size_t)CVT_BLOCKS * 256) {
            float4 v = x[i];
            out[i * 2]     = __floats2half2_rn(v.x, v.y);
            out[i * 2 + 1] = __floats2half2_rn(v.z, v.w);
        }
    }
}

// --------------------------------------------------------------- GEMM kernel -
// Persistent: each CTA processes tiles bid, bid+G, ... with one continuous
// 2-slot cp.async + mbarrier pipeline (BK=128 -> half the stage boundaries).
__global__ __launch_bounds__(256, 1)
void gemm_kernel(const float* __restrict__ bias, float* __restrict__ y)
{
    extern __shared__ __align__(128) unsigned char smem[];
    const uint32_t sbase = (uint32_t)__cvta_generic_to_shared(smem);
    const uint32_t tiles = sbase + 128;
    const int tid  = threadIdx.x;
    const int lane = tid & 31;
    const int wid  = tid >> 5;
    const int wm   = wid & 1;      // 2 M groups of 64
    const int wn   = wid >> 1;     // 4 N groups of 64

    if (tid == 0) {
        #pragma unroll
        for (int s = 0; s < STAGES; s++) {
            mbar_init(sbase + s * 16,     256);  // full
            mbar_init(sbase + s * 16 + 8,   8);  // empty
        }
    }
    __syncthreads();

    const int bid = blockIdx.x;
    const int G   = gridDim.x;
    const int ntiles = (TT - bid + G - 1) / G;
    const int NSTG   = ntiles * KT;              // total stages for this CTA

    auto tile_mn = [&](int i, int& m0, int& n0) {
        const int t = bid + i * G;
        m0 = (t / NT) * BM;
        n0 = (t % NT) * BN;
    };

    auto load_global = [&](int l) {              // l = continuous stage index
        const int kt   = l & 31;
        const int slot = l & 1;
        int m0, n0; tile_mn(l >> 5, m0, n0);
        const uint32_t sa = tiles + slot * STAGE_BYTES;
        const uint32_t sb = sa + A_BYTES;
        const __half* ga = g_xh + (size_t)m0 * KDIM + kt * BK;
        const __half* gb = g_Wh + (size_t)n0 * KDIM + kt * BK;
        #pragma unroll
        for (int i = 0; i < 8; i++) {            // A: 2048 16B chunks
            int chunk = i * 256 + tid;
            int r = chunk >> 4, c = chunk & 15;
            uint32_t so = sa + swz(r, c);
            const __half* g = ga + (size_t)r * KDIM + c * 8;
            asm volatile("cp.async.cg.shared.global [%0], [%1], 16;" :: "r"(so), "l"(g));
        }
        #pragma unroll
        for (int i = 0; i < 16; i++) {           // B: 4096 16B chunks
            int chunk = i * 256 + tid;
            int r = chunk >> 4, c = chunk & 15;
            uint32_t so = sb + swz(r, c);
            const __half* g = gb + (size_t)r * KDIM + c * 8;
            asm volatile("cp.async.cg.shared.global [%0], [%1], 16;" :: "r"(so), "l"(g));
        }
        cpasync_mbar_arrive(sbase + slot * 16);  // full[slot]
    };

    float acc[4][8][4];
    #pragma unroll
    for (int i = 0; i < 4; i++)
        #pragma unroll
        for (int j = 0; j < 8; j++)
            #pragma unroll
            for (int k = 0; k < 4; k++) acc[i][j][k] = 0.f;

    const int br_base = wn * 64 + ((lane >> 4) << 3) + (lane & 7);   // + q*16
    const int bc_sel  = (lane >> 3) & 1;                             // + 2*ks
    const int ar_base = wm * 64 + (lane & 15);                       // + mt*16
    const int ac_sel  = lane >> 4;                                   // + 2*ks

    auto compute_stage = [&](int slot) {
        const uint32_t sa = tiles + slot * STAGE_BYTES;
        const uint32_t sb = sa + A_BYTES;

        uint32_t bf[2][16];  // B frags (n64), double-buffered over ks
        uint32_t af[2][4];   // A frags, double-buffered over mt

        auto ldB = [&](int ks, uint32_t* dst) {
            #pragma unroll
            for (int q = 0; q < 4; q++) {
                int r = br_base + q * 16;
                uint32_t addr = sb + swz(r, 2 * ks + bc_sel);
                asm volatile("ldmatrix.sync.aligned.m8n8.x4.shared.b16 {%0,%1,%2,%3}, [%4];"
                    : "=r"(dst[q*4+0]), "=r"(dst[q*4+1]), "=r"(dst[q*4+2]), "=r"(dst[q*4+3])
                    : "r"(addr));
            }
        };
        auto ldA = [&](int ks, int mt, uint32_t* dst) {
            int r = ar_base + mt * 16;
            uint32_t addr = sa + swz(r, 2 * ks + ac_sel);
            asm volatile("ldmatrix.sync.aligned.m8n8.x4.shared.b16 {%0,%1,%2,%3}, [%4];"
                : "=r"(dst[0]), "=r"(dst[1]), "=r"(dst[2]), "=r"(dst[3])
                : "r"(addr));
        };

        ldB(0, bf[0]);
        ldA(0, 0, af[0]);

        #pragma unroll
        for (int ks = 0; ks < 8; ks++) {         // 8 x k16 per BK=128
            if (ks < 7) ldB(ks + 1, bf[(ks + 1) & 1]);
            const uint32_t* b = bf[ks & 1];
            #pragma unroll
            for (int mt = 0; mt < 4; mt++) {
                if (mt < 3)      ldA(ks,     mt + 1, af[(mt + 1) & 1]);
                else if (ks < 7) ldA(ks + 1, 0,      af[0]);
                const uint32_t* a = af[mt & 1];
                #pragma unroll
                for (int nt = 0; nt < 8; nt++) {
                    asm volatile(
                        "mma.sync.aligned.m16n8k16.row.col.f32.f16.f16.f32 "
                        "{%0,%1,%2,%3},{%4,%5,%6,%7},{%8,%9},{%0,%1,%2,%3};"
                        : "+f"(acc[mt][nt][0]), "+f"(acc[mt][nt][1]),
                          "+f"(acc[mt][nt][2]), "+f"(acc[mt][nt][3])
                        : "r"(a[0]), "r"(a[1]), "r"(a[2]), "r"(a[3]),
                          "r"(b[(nt >> 1) * 4 + (nt & 1) * 2]),
                          "r"(b[(nt >> 1) * 4 + (nt & 1) * 2 + 1]));
                }
            }
        }
    };

    // prologue: fill slot 0
    load_global(0);

    const int g_ep = lane >> 2;
    const int tig  = lane & 3;

    for (int g = 0; g < NSTG; g++) {
        const int ls = g + 1;
        if (ls < NSTG) {
            const int s = ls & 1;
            if (ls >= STAGES)
                mbar_wait(sbase + s * 16 + 8, ((ls / STAGES) - 1) & 1);  // empty[s]
            load_global(ls);
        }
        const int cs = g & 1;
        mbar_wait(sbase + cs * 16, (g / STAGES) & 1);                    // full[cs]
        compute_stage(cs);
        __syncwarp();
        if (lane == 0) mbar_arrive(sbase + cs * 16 + 8);                 // empty[cs]

        if ((g & 31) == 31) {
            // ---- per-tile epilogue (next tile's loads already in flight) ----
            int m0, n0; tile_mn(g >> 5, m0, n0);
            #pragma unroll
            for (int mt = 0; mt < 4; mt++) {
                const int row = m0 + wm * 64 + mt * 16 + g_ep;
                #pragma unroll
                for (int nt = 0; nt < 8; nt++) {
                    const int col = n0 + wn * 64 + nt * 8 + tig * 2;
                    const float b0 = __ldg(bias + col), b1 = __ldg(bias + col + 1);
                    float2 v0 = make_float2(acc[mt][nt][0] + b0, acc[mt][nt][1] + b1);
                    float2 v1 = make_float2(acc[mt][nt][2] + b0, acc[mt][nt][3] + b1);
                    *reinterpret_cast<float2*>(y + (size_t)row       * NDIM + col) = v0;
                    *reinterpret_cast<float2*>(y + (size_t)(row + 8) * NDIM + col) = v1;
                    acc[mt][nt][0] = 0.f; acc[mt][nt][1] = 0.f;
                    acc[mt][nt][2] = 0.f; acc[mt][nt][3] = 0.f;
                }
            }
        }
    }
}

// ------------------------------------------------------------------- host ----
extern "C" void kernel_launch(void* const* d_in, const int* in_sizes, int n_in,
                              void* d_out, int out_size) {
    const float* x      = (const float*)d_in[0];
    const float* values = (const float*)d_in[1];
    const int*   col    = (const int*)d_in[2];
    const float* bias   = (const float*)d_in[3];
    float* y = (float*)d_out;

    static int sms = 0;
    if (sms == 0) {
        cudaDeviceGetAttribute(&sms, cudaDevAttrMultiProcessorCount, 0);
        if (sms <= 0) sms = 148;
        cudaFuncSetAttribute(gemm_kernel, cudaFuncAttributeMaxDynamicSharedMemorySize, SMEM_SIZE);
    }

    prep_kernel<<<PREP_BLOCKS, 256>>>(values, col, (const float4*)x);
    gemm_kernel<<<sms, 256, SMEM_SIZE>>>(bias, y);
}

// round 17
// speedup vs baseline: 1.0178x; 1.0178x over previous
#include <cuda_runtime.h>
#include <cuda_fp16.h>
#include <cstdint>

// Problem dims
#define B_ROWS 8192
#define KDIM   4096
#define NDIM   4096
#define CAPQ   492

// GEMM tiling: CTA 128x256, 8 warps as 2(M) x 4(N), warp tile 64x64.
// 4-stage cp.async + mbarrier pipeline; load-issue staggered across SMSP pairs.
#define BM 128
#define BN 256
#define BK 64                          // 64 halves = 128 B rows
#define STAGES 4
#define MT (B_ROWS / BM)               // 64
#define NT (NDIM / BN)                 // 16
#define KT (KDIM / BK)                 // 64
#define A_BYTES (BM * BK * 2)          // 16384
#define B_BYTES (BN * BK * 2)          // 32768
#define STAGE_BYTES (A_BYTES + B_BYTES)      // 49152
#define SMEM_SIZE (128 + STAGES * STAGE_BYTES)   // 196736

// Scratch (allocations forbidden -> __device__ globals)
__device__ __half g_Wh[(size_t)NDIM * KDIM];   // half W, [n][k]
__device__ __half g_xh[(size_t)B_ROWS * KDIM]; // half x, [m][k]

// ----------------------------------------------------------- mbarrier utils -
__device__ __forceinline__ void mbar_init(uint32_t a, uint32_t cnt) {
    asm volatile("mbarrier.init.shared.b64 [%0], %1;" :: "r"(a), "r"(cnt) : "memory");
}
__device__ __forceinline__ void mbar_arrive(uint32_t a) {
    asm volatile("mbarrier.arrive.shared.b64 _, [%0];" :: "r"(a) : "memory");
}
__device__ __forceinline__ void cpasync_mbar_arrive(uint32_t a) {
    // .noinc is load-bearing (default form pre-increments expected count -> hang)
    asm volatile("cp.async.mbarrier.arrive.noinc.shared.b64 [%0];" :: "r"(a) : "memory");
}
// acquire-form wait: ordering built into the trywait, no separate fence
__device__ __forceinline__ void mbar_wait(uint32_t a, uint32_t parity) {
    uint32_t done;
    asm volatile(
        "{\n\t.reg .pred p;\n\t"
        "mbarrier.try_wait.parity.acquire.cta.shared::cta.b64 p, [%1], %2;\n\t"
        "selp.b32 %0, 1, 0, p;\n\t}"
        : "=r"(done) : "r"(a), "r"(parity) : "memory");
    while (!done) {
        asm volatile(
            "{\n\t.reg .pred p;\n\t"
            "mbarrier.try_wait.parity.acquire.cta.shared::cta.b64 p, [%1], %2, 0x989680;\n\t"
            "selp.b32 %0, 1, 0, p;\n\t}"
            : "=r"(done) : "r"(a), "r"(parity) : "memory");
    }
}

// ------------------------------------------------------------ fused prep ----
// Interleaved block types: bid%3==0 -> cvt x (2048 blocks), else build_w (4096).
#define CVT_BLOCKS 2048
#define PREP_BLOCKS (NDIM + CVT_BLOCKS)   // 6144
__global__ __launch_bounds__(256)
void prep_kernel(const float* __restrict__ values, const int* __restrict__ col,
                 const float4* __restrict__ x) {
    __shared__ float row[KDIM];
    const int tid = threadIdx.x;
    const int bid = blockIdx.x;

    if (bid % 3 != 0) {
        const int o = bid - bid / 3 - 1;          // 0..NDIM-1
        float4* r4 = (float4*)row;
        #pragma unroll
        for (int i = 0; i < KDIM / 4 / 256; i++)
            r4[i * 256 + tid] = make_float4(0.f, 0.f, 0.f, 0.f);
        __syncthreads();

        const float* v = values + (size_t)o * CAPQ;
        const int*   c = col    + (size_t)o * CAPQ;
        for (int s = tid; s < CAPQ; s += 256) {
            float val = v[s];
            if (val != 0.0f) atomicAdd(&row[c[s]], val);
        }
        __syncthreads();

        __half2* out = (__half2*)(g_Wh + (size_t)o * KDIM);
        #pragma unroll
        for (int i = 0; i < KDIM / 4 / 256; i++) {
            float4 f = r4[i * 256 + tid];
            int j = (i * 256 + tid) * 2;
            out[j]     = __floats2half2_rn(f.x, f.y);
            out[j + 1] = __floats2half2_rn(f.z, f.w);
        }
    } else {
        const int cb = bid / 3;                   // 0..CVT_BLOCKS-1
        const size_t n4 = (size_t)B_ROWS * KDIM / 4;
        __half2* out = (__half2*)g_xh;
        for (size_t i = (size_t)cb * 256 + tid; i < n4;
             i += (size_t)CVT_BLOCKS * 256) {
            float4 v = x[i];
            out[i * 2]     = __floats2half2_rn(v.x, v.y);
            out[i * 2 + 1] = __floats2half2_rn(v.z, v.w);
        }
    }
}

// --------------------------------------------------------------- GEMM kernel -
// 256 threads = 8 warps in 2(M) x 4(N); warp tile 64x64; mma.m16n8k16 f16->f32.
// Warps 0-3 issue stage loads BEFORE the full-wait, warps 4-7 AFTER compute:
// each SMSP (wid&3) pairs one early and one late warp, so LDGSTS issue
// throttle on one warp overlaps the other's HMMA stream.
__global__ __launch_bounds__(256, 1)
void gemm_kernel(const float* __restrict__ bias, float* __restrict__ y)
{
    extern __shared__ __align__(128) unsigned char smem[];
    const uint32_t sbase = (uint32_t)__cvta_generic_to_shared(smem);
    const uint32_t tiles = sbase + 128;
    const int tid  = threadIdx.x;
    const int lane = tid & 31;
    const int wid  = tid >> 5;
    const int wm   = wid & 1;      // 2 M groups of 64
    const int wn   = wid >> 1;     // 4 N groups of 64
    const bool load_early = (wid < 4);

    if (tid == 0) {
        #pragma unroll
        for (int s = 0; s < STAGES; s++) {
            mbar_init(sbase + s * 16,     256);  // full
            mbar_init(sbase + s * 16 + 8,   8);  // empty
        }
    }
    __syncthreads();

    const int m0 = (blockIdx.x / NT) * BM;
    const int n0 = (blockIdx.x % NT) * BN;

    const __half* Ag = g_xh + (size_t)m0 * KDIM;
    const __half* Bg = g_Wh + (size_t)n0 * KDIM;

    auto load_stage = [&](int kt, int slot) {
        const uint32_t sa = tiles + slot * STAGE_BYTES;
        const uint32_t sb = sa + A_BYTES;
        const __half* ga = Ag + kt * BK;
        const __half* gb = Bg + kt * BK;
        #pragma unroll
        for (int i = 0; i < 4; i++) {            // A: 1024 16B chunks
            int chunk = i * 256 + tid;
            int r = chunk >> 3, c = chunk & 7;
            uint32_t so = sa + r * 128 + ((c ^ (r & 7)) << 4);
            const __half* g = ga + (size_t)r * KDIM + c * 8;
            asm volatile("cp.async.cg.shared.global [%0], [%1], 16;" :: "r"(so), "l"(g));
        }
        #pragma unroll
        for (int i = 0; i < 8; i++) {            // B: 2048 16B chunks
            int chunk = i * 256 + tid;
            int r = chunk >> 3, c = chunk & 7;
            uint32_t so = sb + r * 128 + ((c ^ (r & 7)) << 4);
            const __half* g = gb + (size_t)r * KDIM + c * 8;
            asm volatile("cp.async.cg.shared.global [%0], [%1], 16;" :: "r"(so), "l"(g));
        }
        cpasync_mbar_arrive(sbase + slot * 16);  // full[slot]
    };

    float acc[4][8][4];
    #pragma unroll
    for (int i = 0; i < 4; i++)
        #pragma unroll
        for (int j = 0; j < 8; j++)
            #pragma unroll
            for (int k = 0; k < 4; k++) acc[i][j][k] = 0.f;

    const int br_base = wn * 64 + ((lane >> 4) << 3) + (lane & 7);   // + q*16
    const int bc_sel  = (lane >> 3) & 1;                             // + 2*ks
    const int ar_base = wm * 64 + (lane & 15);                       // + mt*16
    const int ac_sel  = lane >> 4;                                   // + 2*ks

    auto compute_stage = [&](int slot) {
        const uint32_t sa = tiles + slot * STAGE_BYTES;
        const uint32_t sb = sa + A_BYTES;

        uint32_t bf[2][16];  // B frags (n64), double-buffered over ks
        uint32_t af[2][4];   // A frags, double-buffered over mt

        auto ldB = [&](int ks, uint32_t* dst) {
            #pragma unroll
            for (int q = 0; q < 4; q++) {
                int r = br_base + q * 16;
                int c = 2 * ks + bc_sel;
                uint32_t addr = sb + r * 128 + ((c ^ (r & 7)) << 4);
                asm volatile("ldmatrix.sync.aligned.m8n8.x4.shared.b16 {%0,%1,%2,%3}, [%4];"
                    : "=r"(dst[q*4+0]), "=r"(dst[q*4+1]), "=r"(dst[q*4+2]), "=r"(dst[q*4+3])
                    : "r"(addr));
            }
        };
        auto ldA = [&](int ks, int mt, uint32_t* dst) {
            int r = ar_base + mt * 16;
            int c = 2 * ks + ac_sel;
            uint32_t addr = sa + r * 128 + ((c ^ (r & 7)) << 4);
            asm volatile("ldmatrix.sync.aligned.m8n8.x4.shared.b16 {%0,%1,%2,%3}, [%4];"
                : "=r"(dst[0]), "=r"(dst[1]), "=r"(dst[2]), "=r"(dst[3])
                : "r"(addr));
        };

        ldB(0, bf[0]);
        ldA(0, 0, af[0]);

        #pragma unroll
        for (int ks = 0; ks < 4; ks++) {
            if (ks < 3) ldB(ks + 1, bf[(ks + 1) & 1]);
            const uint32_t* b = bf[ks & 1];
            #pragma unroll
            for (int mt = 0; mt < 4; mt++) {
                if (mt < 3)      ldA(ks,     mt + 1, af[(mt + 1) & 1]);
                else if (ks < 3) ldA(ks + 1, 0,      af[0]);
                const uint32_t* a = af[mt & 1];
                #pragma unroll
                for (int nt = 0; nt < 8; nt++) {
                    asm volatile(
                        "mma.sync.aligned.m16n8k16.row.col.f32.f16.f16.f32 "
                        "{%0,%1,%2,%3},{%4,%5,%6,%7},{%8,%9},{%0,%1,%2,%3};"
                        : "+f"(acc[mt][nt][0]), "+f"(acc[mt][nt][1]),
                          "+f"(acc[mt][nt][2]), "+f"(acc[mt][nt][3])
                        : "r"(a[0]), "r"(a[1]), "r"(a[2]), "r"(a[3]),
                          "r"(b[(nt >> 1) * 4 + (nt & 1) * 2]),
                          "r"(b[(nt >> 1) * 4 + (nt & 1) * 2 + 1]));
                }
            }
        }
    };

    // prologue: fill 3 of 4 stages (all warps)
    load_stage(0, 0);
    load_stage(1, 1);
    load_stage(2, 2);

    for (int kt = 0; kt < KT; kt++) {
        const int ls = kt + 3;
        const int s  = ls & 3;

        if (ls < KT && load_early) {
            if (ls >= STAGES)
                mbar_wait(sbase + s * 16 + 8, ((ls / STAGES) - 1) & 1);  // empty[s]
            load_stage(ls, s);
        }

        const int cs = kt & 3;
        mbar_wait(sbase + cs * 16, (kt / STAGES) & 1);                   // full[cs]
        compute_stage(cs);

        if (ls < KT && !load_early) {
            if (ls >= STAGES)
                mbar_wait(sbase + s * 16 + 8, ((ls / STAGES) - 1) & 1);  // empty[s]
            load_stage(ls, s);
        }

        __syncwarp();
        if (lane == 0) mbar_arrive(sbase + cs * 16 + 8);                 // empty[cs]
    }

    // ---- epilogue ----
    const int g   = lane >> 2;
    const int tig = lane & 3;
    #pragma unroll
    for (int mt = 0; mt < 4; mt++) {
        const int row = m0 + wm * 64 + mt * 16 + g;
        #pragma unroll
        for (int nt = 0; nt < 8; nt++) {
            const int col = n0 + wn * 64 + nt * 8 + tig * 2;
            const float b0 = __ldg(bias + col), b1 = __ldg(bias + col + 1);
            float2 v0 = make_float2(acc[mt][nt][0] + b0, acc[mt][nt][1] + b1);
            float2 v1 = make_float2(acc[mt][nt][2] + b0, acc[mt][nt][3] + b1);
            *reinterpret_cast<float2*>(y + (size_t)row       * NDIM + col) = v0;
            *reinterpret_cast<float2*>(y + (size_t)(row + 8) * NDIM + col) = v1;
        }
    }
}

// ------------------------------------------------------------------- host ----
extern "C" void kernel_launch(void* const* d_in, const int* in_sizes, int n_in,
                              void* d_out, int out_size) {
    const float* x      = (const float*)d_in[0];
    const float* values = (const float*)d_in[1];
    const int*   col    = (const int*)d_in[2];
    const float* bias   = (const float*)d_in[3];
    float* y = (float*)d_out;

    prep_kernel<<<PREP_BLOCKS, 256>>>(values, col, (const float4*)x);

    static bool attr_set = false;
    if (!attr_set) {
        cudaFuncSetAttribute(gemm_kernel, cudaFuncAttributeMaxDynamicSharedMemorySize, SMEM_SIZE);
        attr_set = true;
    }
    gemm_kernel<<<MT * NT, 256, SMEM_SIZE>>>(bias, y);
}